// round 8
// baseline (speedup 1.0000x reference)
#include <cuda_runtime.h>

#define B_   4096
#define T_   168
#define P_   16
#define EPB  32
#define NT   384
#define LHALF 192
#define AST  34

typedef unsigned long long ull;

#define BAR_SYNC(id, n)   asm volatile("bar.sync %0, %1;"   :: "r"(id), "r"(n) : "memory")
#define BAR_ARRIVE(id, n) asm volatile("bar.arrive %0, %1;" :: "r"(id), "r"(n) : "memory")

__device__ __forceinline__ ull dup2(float w) {
    ull r; unsigned u = __float_as_uint(w);
    asm("mov.b64 %0, {%1, %1};" : "=l"(r) : "r"(u));
    return r;
}
__device__ __forceinline__ void fma2(ull& a, ull v, ull w) {
    asm("fma.rn.f32x2 %0, %1, %2, %0;" : "+l"(a) : "l"(v), "l"(w));
}

__device__ __forceinline__ float fsig(float v) {
    return __fdividef(1.0f, 1.0f + __expf(-v));
}
__device__ __forceinline__ float ftanh(float v) {
    float e = __expf(2.0f * v);
    return 1.0f - __fdividef(2.0f, e + 1.0f);
}

// one state load feeds TWO gate rows: 4 LDS.128-equivalents -> 8 FFMA2
template<int K, int STRIDE>
__device__ __forceinline__ void accum2(const float* s, int e0,
                                       const float* wA, const float* wB,
                                       ull& a0, ull& a1, ull& a2, ull& a3,
                                       ull& b0, ull& b1, ull& b2, ull& b3) {
    #pragma unroll
    for (int k = 0; k < K; k++) {
        ulonglong2 vA = *(const ulonglong2*)(s + k * STRIDE + e0);
        ulonglong2 vB = *(const ulonglong2*)(s + k * STRIDE + e0 + 4);
        ull wpA = dup2(wA[k]);
        ull wpB = dup2(wB[k]);
        fma2(a0, vA.x, wpA); fma2(a1, vA.y, wpA);
        fma2(a2, vB.x, wpA); fma2(a3, vB.y, wpA);
        fma2(b0, vA.x, wpB); fma2(b1, vA.y, wpB);
        fma2(b2, vB.x, wpB); fma2(b3, vB.y, wpB);
    }
}

__device__ __forceinline__ float act_one(const float* sa, int jj, int e, float& c) {
    float vi = fsig (sa[( 0 + jj) * AST + e]);
    float vf = fsig (sa[(24 + jj) * AST + e]);
    float vg = ftanh(sa[(48 + jj) * AST + e]);
    float vo = fsig (sa[(72 + jj) * AST + e]);
    c = vf * c + vi * vg;
    return vo * ftanh(c);
}

__device__ __forceinline__ void store_gates(float* sa, int base,
                                            ull a0, ull a1, ull a2, ull a3) {
    *(ull*)(sa + base + 0) = a0;
    *(ull*)(sa + base + 2) = a1;
    *(ull*)(sa + base + 4) = a2;
    *(ull*)(sa + base + 6) = a3;
}

__global__ __launch_bounds__(NT, 1) void lstm_fused_kernel(
    const float* __restrict__ x,
    const float* __restrict__ Wih1, const float* __restrict__ Whh1,
    const float* __restrict__ bih1, const float* __restrict__ bhh1,
    const float* __restrict__ Wih2, const float* __restrict__ Whh2,
    const float* __restrict__ bih2, const float* __restrict__ bhh2,
    const float* __restrict__ W1,   const float* __restrict__ b1,
    const float* __restrict__ W2,   const float* __restrict__ b2,
    float* __restrict__ out)
{
    __shared__ __align__(16) float s_x    [16 * 36];
    __shared__ __align__(16) float s_h1raw[24 * 32];
    __shared__ __align__(16) float s_h1t  [2][24 * 32];
    __shared__ __align__(16) float s_h2raw[24 * 32];
    __shared__ __align__(16) float s_feat [24 * 32];
    __shared__ __align__(8)  float s_a1[96 * AST];
    __shared__ __align__(8)  float s_a2[96 * AST];

    const int tid   = threadIdx.x;
    const int bbase = blockIdx.x * EPB;
    const bool isL1 = tid < LHALF;
    const int  u    = isL1 ? tid : tid - LHALF;
    const int  wl   = u % 48;            // row pair (wl, wl+48)
    const int  e0   = (u / 48) * 8;      // k-loop batch-elem base (8 per thread)
    const int  e    = u & 31;            // act-phase batch elem
    const int  js   = u >> 5;            // act-phase j slot (0..5): j = js+6q

    // ---- init state + stage x[0] ----
    s_h1raw[tid] = 0.f;  s_h1raw[tid + 384] = 0.f;
    s_h2raw[tid] = 0.f;  s_h2raw[tid + 384] = 0.f;
    for (int i = tid; i < EPB * P_; i += NT) {
        int ee = i >> 4, f = i & 15;
        s_x[f * 36 + ee] = x[((bbase + ee) * (long)T_) * P_ + f];
    }

    // ---- per-thread register weights: 2 gate rows ----
    float wr[96];
    ull biasA, biasB;
    if (isL1) {
        int rA = wl, rB = wl + 48;
        #pragma unroll
        for (int k = 0; k < 16; k++) { wr[k]      = Wih1[rA * 16 + k];
                                       wr[40 + k] = Wih1[rB * 16 + k]; }
        #pragma unroll
        for (int k = 0; k < 24; k++) { wr[16 + k] = Whh1[rA * 24 + k];
                                       wr[56 + k] = Whh1[rB * 24 + k]; }
        biasA = dup2(bih1[rA] + bhh1[rA]);
        biasB = dup2(bih1[rB] + bhh1[rB]);
    } else {
        int rA = wl, rB = wl + 48;
        #pragma unroll
        for (int k = 0; k < 24; k++) { wr[k]      = Wih2[rA * 24 + k];
                                       wr[24 + k] = Whh2[rA * 24 + k];
                                       wr[48 + k] = Wih2[rB * 24 + k];
                                       wr[72 + k] = Whh2[rB * 24 + k]; }
        biasA = dup2(bih2[rA] + bhh2[rA]);
        biasB = dup2(bih2[rB] + bhh2[rB]);
    }
    __syncthreads();

    float c[4] = {0.f, 0.f, 0.f, 0.f};

    if (isL1) {
        // ======== layer-1 half: 6 warps ========
        for (int t = 0; t < T_; t++) {
            // prefetch x[t+1] (512 slots over 192 threads)
            float xp0 = 0.f, xp1 = 0.f, xp2 = 0.f;
            if (t + 1 < T_) {
                xp0 = x[((bbase + (tid >> 4)) * (long)T_ + (t + 1)) * P_ + (tid & 15)];
                { int i1 = tid + 192;
                  xp1 = x[((bbase + (i1 >> 4)) * (long)T_ + (t + 1)) * P_ + (i1 & 15)]; }
                if (tid < 128) {
                  int i2 = tid + 384;
                  xp2 = x[((bbase + (i2 >> 4)) * (long)T_ + (t + 1)) * P_ + (i2 & 15)]; }
            }
            // k-loop: gates(t) from x(t), h1(t-1), two rows per thread
            ull a0 = biasA, a1 = biasA, a2 = biasA, a3 = biasA;
            ull b0 = biasB, b1 = biasB, b2 = biasB, b3 = biasB;
            accum2<16, 36>(s_x,     e0, wr,      wr + 40, a0,a1,a2,a3, b0,b1,b2,b3);
            accum2<24, 32>(s_h1raw, e0, wr + 16, wr + 56, a0,a1,a2,a3, b0,b1,b2,b3);
            store_gates(s_a1,  wl       * AST + e0, a0, a1, a2, a3);
            store_gates(s_a1, (wl + 48) * AST + e0, b0, b1, b2, b3);
            BAR_SYNC(2, LHALF);
            if (t >= 2) BAR_SYNC(5 + 2 * (t & 1), NT);   // L2 freed buffer (t&1)
            // activation: 4 j per thread
            float* buf = s_h1t[t & 1];
            #pragma unroll
            for (int q = 0; q < 4; q++) {
                int j = js + 6 * q;
                float h = act_one(s_a1, j, e, c[q]);
                s_h1raw[j * 32 + e] = h;
                buf    [j * 32 + e] = ftanh(h);
            }
            // commit x prefetch (s_x reads done at BAR 2)
            if (t + 1 < T_) {
                s_x[(tid & 15) * 36 + (tid >> 4)] = xp0;
                { int i1 = tid + 192; s_x[(i1 & 15) * 36 + (i1 >> 4)] = xp1; }
                if (tid < 128) { int i2 = tid + 384; s_x[(i2 & 15) * 36 + (i2 >> 4)] = xp2; }
            }
            BAR_ARRIVE(4 + 2 * (t & 1), NT);             // h1t(t) ready for L2
            BAR_SYNC(3, LHALF);
        }
    } else {
        // ======== layer-2 half: 6 warps, one step behind ========
        for (int t = 0; t < T_; t++) {
            BAR_SYNC(4 + 2 * (t & 1), NT);               // wait h1t(t)
            ull a0 = biasA, a1 = biasA, a2 = biasA, a3 = biasA;
            ull b0 = biasB, b1 = biasB, b2 = biasB, b3 = biasB;
            accum2<24, 32>(s_h1t[t & 1], e0, wr,      wr + 48, a0,a1,a2,a3, b0,b1,b2,b3);
            accum2<24, 32>(s_h2raw,      e0, wr + 24, wr + 72, a0,a1,a2,a3, b0,b1,b2,b3);
            BAR_ARRIVE(5 + 2 * (t & 1), NT);             // buffer (t&1) free
            store_gates(s_a2,  wl       * AST + e0, a0, a1, a2, a3);
            store_gates(s_a2, (wl + 48) * AST + e0, b0, b1, b2, b3);
            BAR_SYNC(8, LHALF);
            #pragma unroll
            for (int q = 0; q < 4; q++) {
                int j = js + 6 * q;
                float h = act_one(s_a2, j, e, c[q]);
                s_h2raw[j * 32 + e] = h;
                if (t == T_ - 1) s_feat[j * 32 + e] = ftanh(h);
            }
            BAR_SYNC(9, LHALF);
        }
    }
    __syncthreads();

    // ---- head MLP ----
    for (int i = tid; i < EPB * 16; i += NT) {
        int uo = i & 15, ee = i >> 4;
        float acc = b1[uo];
        #pragma unroll
        for (int k = 0; k < 24; k++) acc += W1[uo * 24 + k] * s_feat[k * 32 + ee];
        s_a1[ee * 16 + uo] = fmaxf(acc, 0.f);
    }
    __syncthreads();
    for (int i = tid; i < EPB * 24; i += NT) {
        int uu = i % 24, ee = i / 24;
        float acc = b2[uu];
        #pragma unroll
        for (int k = 0; k < 16; k++) acc += W2[uu * 16 + k] * s_a1[ee * 16 + k];
        out[(bbase + ee) * 24 + uu] = acc;
    }
}

extern "C" void kernel_launch(void* const* d_in, const int* in_sizes, int n_in,
                              void* d_out, int out_size)
{
    const float* x    = (const float*)d_in[0];
    const float* Wih1 = (const float*)d_in[1];
    const float* Whh1 = (const float*)d_in[2];
    const float* bih1 = (const float*)d_in[3];
    const float* bhh1 = (const float*)d_in[4];
    const float* Wih2 = (const float*)d_in[5];
    const float* Whh2 = (const float*)d_in[6];
    const float* bih2 = (const float*)d_in[7];
    const float* bhh2 = (const float*)d_in[8];
    const float* W1   = (const float*)d_in[9];
    const float* b1   = (const float*)d_in[10];
    const float* W2   = (const float*)d_in[11];
    const float* b2   = (const float*)d_in[12];

    lstm_fused_kernel<<<B_ / EPB, NT>>>(x, Wih1, Whh1, bih1, bhh1,
                                        Wih2, Whh2, bih2, bhh2,
                                        W1, b1, W2, b2, (float*)d_out);
}

// round 9
// speedup vs baseline: 1.2494x; 1.2494x over previous
#include <cuda_runtime.h>

#define B_   4096
#define T_   168
#define P_   16
#define EPB  16
#define NT   384
#define LHALF 192
#define AST  18          // s_a row stride (even -> STS.64 aligned)

typedef unsigned long long ull;

#define BAR_SYNC(id, n)   asm volatile("bar.sync %0, %1;"   :: "r"(id), "r"(n) : "memory")
#define BAR_ARRIVE(id, n) asm volatile("bar.arrive %0, %1;" :: "r"(id), "r"(n) : "memory")

__device__ __forceinline__ ull dup2(float w) {
    ull r; unsigned u = __float_as_uint(w);
    asm("mov.b64 %0, {%1, %1};" : "=l"(r) : "r"(u));
    return r;
}
__device__ __forceinline__ void fma2(ull& a, ull v, ull w) {
    asm("fma.rn.f32x2 %0, %1, %2, %0;" : "+l"(a) : "l"(v), "l"(w));
}

__device__ __forceinline__ float fsig(float v) {
    return __fdividef(1.0f, 1.0f + __expf(-v));
}
__device__ __forceinline__ float ftanh(float v) {
    float e = __expf(2.0f * v);
    return 1.0f - __fdividef(2.0f, e + 1.0f);
}

// K rows of state (stride STRIDE floats), broadcast LDS.128, vs register weights
template<int K, int STRIDE>
__device__ __forceinline__ void accum_seg(const float* s, int e0, const float* wr,
                                          ull& a0, ull& a1, ull& a2, ull& a3) {
    #pragma unroll
    for (int k = 0; k < K; k++) {
        ulonglong2 vA = *(const ulonglong2*)(s + k * STRIDE + e0);
        ulonglong2 vB = *(const ulonglong2*)(s + k * STRIDE + e0 + 4);
        ull wp = dup2(wr[k]);
        fma2(a0, vA.x, wp); fma2(a1, vA.y, wp);
        fma2(a2, vB.x, wp); fma2(a3, vB.y, wp);
    }
}

__device__ __forceinline__ float act_one(const float* sa, int jj, int e, float& c) {
    float vi = fsig (sa[( 0 + jj) * AST + e]);
    float vf = fsig (sa[(24 + jj) * AST + e]);
    float vg = ftanh(sa[(48 + jj) * AST + e]);
    float vo = fsig (sa[(72 + jj) * AST + e]);
    c = vf * c + vi * vg;
    return vo * ftanh(c);
}

__device__ __forceinline__ void store_gates(float* sa, int base,
                                            ull a0, ull a1, ull a2, ull a3) {
    *(ull*)(sa + base + 0) = a0;
    *(ull*)(sa + base + 2) = a1;
    *(ull*)(sa + base + 4) = a2;
    *(ull*)(sa + base + 6) = a3;
}

__global__ __launch_bounds__(NT, 2) void lstm_fused_kernel(
    const float* __restrict__ x,
    const float* __restrict__ Wih1, const float* __restrict__ Whh1,
    const float* __restrict__ bih1, const float* __restrict__ bhh1,
    const float* __restrict__ Wih2, const float* __restrict__ Whh2,
    const float* __restrict__ bih2, const float* __restrict__ bhh2,
    const float* __restrict__ W1,   const float* __restrict__ b1,
    const float* __restrict__ W2,   const float* __restrict__ b2,
    float* __restrict__ out)
{
    __shared__ __align__(16) float s_x    [16 * 16];     // [f][e], e contiguous
    __shared__ __align__(16) float s_h1raw[24 * 16];
    __shared__ __align__(16) float s_h1t  [2][24 * 16];
    __shared__ __align__(16) float s_h2raw[24 * 16];
    __shared__ __align__(16) float s_feat [24 * 16];
    __shared__ __align__(8)  float s_a1[96 * AST];
    __shared__ __align__(8)  float s_a2[96 * AST];

    const int tid   = threadIdx.x;
    const int bbase = blockIdx.x * EPB;
    const bool isL1 = tid < LHALF;
    const int  u    = isL1 ? tid : tid - LHALF;
    const int  wl   = u % 96;            // gate row
    const int  e0   = (u / 96) * 8;      // k-loop batch base: {0, 8}
    const int  e    = u & 15;            // act-phase batch elem
    const int  js   = u >> 4;            // act-phase j slot (0..11): j = js, js+12

    // ---- init state + stage x[0] ----
    if (tid < 24 * 16) {
        s_h1raw[tid] = 0.f;  s_h1t[0][tid] = 0.f;  s_h1t[1][tid] = 0.f;
        s_h2raw[tid] = 0.f;
    }
    if (tid < 256) {                      // slot: f = tid>>4, ee = tid&15
        int f = tid >> 4, ee = tid & 15;
        s_x[f * 16 + ee] = x[((bbase + ee) * (long)T_) * P_ + f];
    }

    // ---- per-thread register weights (1 gate row) ----
    float wr[48];
    ull bias;
    if (isL1) {
        #pragma unroll
        for (int k = 0; k < 16; k++) wr[k] = Wih1[wl * 16 + k];
        #pragma unroll
        for (int k = 0; k < 24; k++) wr[16 + k] = Whh1[wl * 24 + k];
        bias = dup2(bih1[wl] + bhh1[wl]);
    } else {
        #pragma unroll
        for (int k = 0; k < 24; k++) wr[k] = Wih2[wl * 24 + k];
        #pragma unroll
        for (int k = 0; k < 24; k++) wr[24 + k] = Whh2[wl * 24 + k];
        bias = dup2(bih2[wl] + bhh2[wl]);
    }
    __syncthreads();

    float ca = 0.f, cb = 0.f;

    if (isL1) {
        // ======== layer-1 half: 6 warps ========
        for (int t = 0; t < T_; t++) {
            // prefetch x[t+1]: 256 slots over 192 threads
            float xp0 = 0.f, xp1 = 0.f;
            if (t + 1 < T_) {
                { int f = tid >> 4, ee = tid & 15;
                  xp0 = x[((bbase + ee) * (long)T_ + (t + 1)) * P_ + f]; }
                if (tid < 64) {
                  int s = tid + 192, f = s >> 4, ee = s & 15;
                  xp1 = x[((bbase + ee) * (long)T_ + (t + 1)) * P_ + f]; }
            }
            // gates(t) = bias + Wih1 x(t) + Whh1 h1(t-1)
            ull a0 = bias, a1 = bias, a2 = bias, a3 = bias;
            accum_seg<16, 16>(s_x,     e0, wr,      a0, a1, a2, a3);
            accum_seg<24, 16>(s_h1raw, e0, wr + 16, a0, a1, a2, a3);
            store_gates(s_a1, wl * AST + e0, a0, a1, a2, a3);
            BAR_SYNC(2, LHALF);
            if (t >= 2) BAR_SYNC(5 + 2 * (t & 1), NT);    // L2 freed buffer (t&1)
            // activation: 2 j per thread
            float* buf = s_h1t[t & 1];
            float h = act_one(s_a1, js, e, ca);
            s_h1raw[js * 16 + e] = h;         buf[js * 16 + e] = ftanh(h);
            h = act_one(s_a1, js + 12, e, cb);
            s_h1raw[(js + 12) * 16 + e] = h;  buf[(js + 12) * 16 + e] = ftanh(h);
            // commit x prefetch (s_x reads all complete at BAR 2)
            if (t + 1 < T_) {
                s_x[(tid >> 4) * 16 + (tid & 15)] = xp0;
                if (tid < 64) { int s = tid + 192; s_x[(s >> 4) * 16 + (s & 15)] = xp1; }
            }
            BAR_ARRIVE(4 + 2 * (t & 1), NT);              // h1t(t) ready for L2
            BAR_SYNC(3, LHALF);
        }
    } else {
        // ======== layer-2 half: 6 warps, one step behind ========
        for (int t = 0; t < T_; t++) {
            BAR_SYNC(4 + 2 * (t & 1), NT);                // wait h1t(t)
            ull a0 = bias, a1 = bias, a2 = bias, a3 = bias;
            accum_seg<24, 16>(s_h1t[t & 1], e0, wr,      a0, a1, a2, a3);
            accum_seg<24, 16>(s_h2raw,      e0, wr + 24, a0, a1, a2, a3);
            BAR_ARRIVE(5 + 2 * (t & 1), NT);              // buffer (t&1) free for L1
            store_gates(s_a2, wl * AST + e0, a0, a1, a2, a3);
            BAR_SYNC(8, LHALF);
            float h = act_one(s_a2, js, e, ca);
            s_h2raw[js * 16 + e] = h;
            if (t == T_ - 1) s_feat[js * 16 + e] = ftanh(h);
            h = act_one(s_a2, js + 12, e, cb);
            s_h2raw[(js + 12) * 16 + e] = h;
            if (t == T_ - 1) s_feat[(js + 12) * 16 + e] = ftanh(h);
            BAR_SYNC(9, LHALF);
        }
    }
    __syncthreads();

    // ---- head MLP: relu(feat @ W1.T + b1) @ W2.T + b2 ----
    if (tid < EPB * 16) {
        int uo = tid & 15, ee = tid >> 4;
        float acc = b1[uo];
        #pragma unroll
        for (int k = 0; k < 24; k++) acc += W1[uo * 24 + k] * s_feat[k * 16 + ee];
        s_a1[ee * 16 + uo] = fmaxf(acc, 0.f);
    }
    __syncthreads();
    {
        int uu = tid % 24, ee = tid / 24;   // 24*16 == 384 == NT
        float acc = b2[uu];
        #pragma unroll
        for (int k = 0; k < 16; k++) acc += W2[uu * 16 + k] * s_a1[ee * 16 + k];
        out[(bbase + ee) * 24 + uu] = acc;
    }
}

extern "C" void kernel_launch(void* const* d_in, const int* in_sizes, int n_in,
                              void* d_out, int out_size)
{
    const float* x    = (const float*)d_in[0];
    const float* Wih1 = (const float*)d_in[1];
    const float* Whh1 = (const float*)d_in[2];
    const float* bih1 = (const float*)d_in[3];
    const float* bhh1 = (const float*)d_in[4];
    const float* Wih2 = (const float*)d_in[5];
    const float* Whh2 = (const float*)d_in[6];
    const float* bih2 = (const float*)d_in[7];
    const float* bhh2 = (const float*)d_in[8];
    const float* W1   = (const float*)d_in[9];
    const float* b1   = (const float*)d_in[10];
    const float* W2   = (const float*)d_in[11];
    const float* b2   = (const float*)d_in[12];

    lstm_fused_kernel<<<B_ / EPB, NT>>>(x, Wih1, Whh1, bih1, bhh1,
                                        Wih2, Whh2, bih2, bhh2,
                                        W1, b1, W2, b2, (float*)d_out);
}